// round 14
// baseline (speedup 1.0000x reference)
#include <cuda_runtime.h>
#include <math.h>

#define N_NODES 100000
#define N_GRAPHS 1000
#define D 64
#define H 128
#define CAP 64            // max in-degree capacity (actual max ~32 for Poisson(10)+ring)
#define ZROW N_NODES      // zero-row index (stays zero: statics zero-init, never written)

// Scratch (alloc-free rule: __device__ globals). cursor/pool/cnt share one
// struct so a single memset clears all per-run state.
struct ZeroRegion {
    int   cursor[N_NODES];      // becomes in-degree after fill
    float pool[N_GRAPHS * D];
    float cnt[N_GRAPHS];
};
__device__ ZeroRegion g_z;
__device__ float g_dinv[N_NODES + 1];          // [ZROW] stays 0
__device__ int   g_esrc[N_NODES * CAP];        // bucketed edge lists (25.6 MB)
__device__ float g_x[(N_NODES + 1) * D];       // +1 zero row for pad loads
__device__ float g_h[(N_NODES + 1) * D];       // +1 zero row for pad loads

// ---------------------------------------------------------------------------
// Bucketed CSR fill: cursor counts in-degree, esrc[d*CAP + pos] = s.
__global__ void fill_kernel(const int* __restrict__ src,
                            const int* __restrict__ dst, int E) {
    int i = blockIdx.x * blockDim.x + threadIdx.x;
    if (i >= E) return;
    int d = dst[i];
    int pos = atomicAdd(&g_z.cursor[d], 1);
    if (pos < CAP) g_esrc[(size_t)d * CAP + pos] = src[i];
}

__global__ void dinv_kernel() {
    int n = blockIdx.x * blockDim.x + threadIdx.x;
    if (n < N_NODES) g_dinv[n] = rsqrtf((float)(min(g_z.cursor[n], CAP) + 1));
}

// ---------------------------------------------------------------------------
// Y[N,64] = X[N,64] @ W[64,64]   (UNSCALED — no shared-state reads, forkable)
__global__ void gemm64_kernel(const float* __restrict__ X,
                              const float* __restrict__ W,
                              float* __restrict__ Y) {
    __shared__ float sW[D * D];
    __shared__ float sx[32 * D];
    int t = threadIdx.x;
    int row0 = blockIdx.x * 32;
    for (int i = t; i < D * D; i += 256) sW[i] = W[i];
    for (int i = t; i < 32 * D; i += 256) sx[i] = X[row0 * D + i];
    __syncthreads();
    int j = t & 63;
    int rg = t >> 6;
    float acc[8];
#pragma unroll
    for (int i = 0; i < 8; i++) acc[i] = 0.f;
#pragma unroll
    for (int k = 0; k < D; k++) {
        float w = sW[k * D + j];
#pragma unroll
        for (int i = 0; i < 8; i++)
            acc[i] += sx[(rg * 8 + i) * D + k] * w;
    }
#pragma unroll
    for (int i = 0; i < 8; i++)
        Y[(row0 + rg * 8 + i) * D + j] = acc[i];
}

// ---------------------------------------------------------------------------
// Gather, half-warp (16 lanes x float4) per node.
//   MODE 1 (layer 1): input X4 is UNSCALED x = emb@W1. Prefetch fetches
//     (src, dinv[src]) pairs; inner step = 2xSHFL + LDG.128 + 4xFFMA.
//     t[n] = dinv[n]*(sum dinv[s]*x[s] + dinv[n]*x[n]);
//     out[n] = relu(t[n] + b)*dinv[n]                       -> write g_h
//   MODE 0 (layer 2): input pre-scaled y'; pure-ADD loop; block-level
//     segmented pool flush (smem stage + fold + sparse red.v4).
template <int MODE>
__global__ void __launch_bounds__(256, 6)
gather_kernel(const float4* __restrict__ X4,
              float4* __restrict__ out,
              const float4* __restrict__ b4,
              const int* __restrict__ batch) {
    int tid = threadIdx.x;
    int node = (blockIdx.x * blockDim.x + tid) >> 4;
    int lane = tid & 31;
    int hl = lane & 15;
    int deg = min(g_z.cursor[node], CAP);
    int maxdeg = max(deg, __shfl_xor_sync(0xffffffffu, deg, 16));
    const int* rowp = g_esrc + (size_t)node * CAP;
    float4 acc0 = make_float4(0.f, 0.f, 0.f, 0.f);
    float4 acc1 = make_float4(0.f, 0.f, 0.f, 0.f);
    for (int j = 0; j < maxdeg; j += 16) {
        int s = ((j + hl) < deg) ? rowp[j + hl] : ZROW;
        float df = (MODE == 1) ? g_dinv[s] : 0.f;
#pragma unroll
        for (int i = 0; i < 16; i += 2) {
            int si0 = __shfl_sync(0xffffffffu, s, (lane & 16) + i);
            int si1 = __shfl_sync(0xffffffffu, s, (lane & 16) + i + 1);
            float4 v0 = X4[(size_t)si0 * 16 + hl];
            float4 v1 = X4[(size_t)si1 * 16 + hl];
            if (MODE == 1) {
                float d0 = __shfl_sync(0xffffffffu, df, (lane & 16) + i);
                float d1 = __shfl_sync(0xffffffffu, df, (lane & 16) + i + 1);
                acc0.x += v0.x * d0; acc0.y += v0.y * d0;
                acc0.z += v0.z * d0; acc0.w += v0.w * d0;
                acc1.x += v1.x * d1; acc1.y += v1.y * d1;
                acc1.z += v1.z * d1; acc1.w += v1.w * d1;
            } else {
                acc0.x += v0.x; acc0.y += v0.y; acc0.z += v0.z; acc0.w += v0.w;
                acc1.x += v1.x; acc1.y += v1.y; acc1.z += v1.z; acc1.w += v1.w;
            }
        }
    }
    // self term + merge accumulators
    float di = rsqrtf((float)(deg + 1));
    float4 xv = X4[(size_t)node * 16 + hl];
    float sc = (MODE == 1) ? di : 1.f;   // self is unscaled in MODE 1
    float4 o;
    o.x = (acc0.x + acc1.x + xv.x * sc) * di;
    o.y = (acc0.y + acc1.y + xv.y * sc) * di;
    o.z = (acc0.z + acc1.z + xv.z * sc) * di;
    o.w = (acc0.w + acc1.w + xv.w * sc) * di;
    if (MODE == 1) {
        float4 bb = b4[hl];
        o.x = fmaxf(o.x + bb.x, 0.f) * di;
        o.y = fmaxf(o.y + bb.y, 0.f) * di;
        o.z = fmaxf(o.z + bb.z, 0.f) * di;
        o.w = fmaxf(o.w + bb.w, 0.f) * di;
        out[(size_t)node * 16 + hl] = o;
    } else {
        // Stage z rows + graph ids in smem; fold segments; sparse flush.
        __shared__ float4 sZ[16][16];   // [node-in-block][column chunk]
        __shared__ int    sB[16];
        int nib = tid >> 4;             // node-in-block 0..15
        sZ[nib][hl] = o;
        if (hl == 0) sB[nib] = __ldg(batch + node);
        __syncthreads();
        if (tid < 16) {
            int c = tid;                // column chunk this thread folds
            float4 z = sZ[0][c];
            int curg = sB[0];
            int run = 1;
            for (int k = 1; k < 16; k++) {
                int bk = sB[k];
                float4 v = sZ[k][c];
                if (bk != curg) {
                    float* p = g_z.pool + curg * D + c * 4;
                    asm volatile("red.global.add.v4.f32 [%0], {%1, %2, %3, %4};"
                                 :: "l"(p), "f"(z.x), "f"(z.y), "f"(z.z), "f"(z.w)
                                 : "memory");
                    if (c == 0) atomicAdd(&g_z.cnt[curg], (float)run);
                    z = v; curg = bk; run = 1;
                } else {
                    z.x += v.x; z.y += v.y; z.z += v.z; z.w += v.w;
                    run++;
                }
            }
            float* p = g_z.pool + curg * D + c * 4;
            asm volatile("red.global.add.v4.f32 [%0], {%1, %2, %3, %4};"
                         :: "l"(p), "f"(z.x), "f"(z.y), "f"(z.z), "f"(z.w)
                         : "memory");
            if (c == 0) atomicAdd(&g_z.cnt[curg], (float)run);
        }
    }
}

// ---------------------------------------------------------------------------
// Head: q = mean(z) @ W2 + b2 ; out = sigmoid(relu(q @ mW1 + mb1) @ mW2 + mb2)
__global__ void mlp_kernel(const float* __restrict__ W2,
                           const float* __restrict__ b2,
                           const float* __restrict__ mW1,
                           const float* __restrict__ mb1,
                           const float* __restrict__ mW2,
                           const float* __restrict__ mb2,
                           float* __restrict__ out) {
    __shared__ float p[D];
    __shared__ float q[D];
    __shared__ float red[H];
    int g = blockIdx.x, t = threadIdx.x;
    if (t < D) {
        float c = fmaxf(g_z.cnt[g], 1.f);
        p[t] = g_z.pool[g * D + t] / c;
    }
    __syncthreads();
    if (t < D) {
        float a = b2[t];
#pragma unroll
        for (int k = 0; k < D; k++) a += p[k] * W2[k * D + t];
        q[t] = a;
    }
    __syncthreads();
    float acc = mb1[t];
#pragma unroll
    for (int k = 0; k < D; k++) acc += q[k] * mW1[k * H + t];
    red[t] = fmaxf(acc, 0.f) * mW2[t];
    __syncthreads();
    for (int s = H / 2; s > 0; s >>= 1) {
        if (t < s) red[t] += red[t + s];
        __syncthreads();
    }
    if (t == 0) out[g] = 1.f / (1.f + expf(-(red[0] + mb2[0])));
}

// ---------------------------------------------------------------------------
extern "C" void kernel_launch(void* const* d_in, const int* in_sizes, int n_in,
                              void* d_out, int out_size) {
    const int*   edge_index = (const int*)d_in[0];
    const int*   batch      = (const int*)d_in[1];
    const float* emb        = (const float*)d_in[2];
    const float* W1         = (const float*)d_in[3];
    const float* b1         = (const float*)d_in[4];
    const float* W2         = (const float*)d_in[5];
    const float* b2         = (const float*)d_in[6];
    const float* mW1        = (const float*)d_in[7];
    const float* mb1        = (const float*)d_in[8];
    const float* mW2        = (const float*)d_in[9];
    const float* mb2        = (const float*)d_in[10];
    float* out = (float*)d_out;

    int E = in_sizes[0] / 2;
    const int* src = edge_index;
    const int* dst = edge_index + E;

    void *p_z, *p_x, *p_h;
    cudaGetSymbolAddress(&p_z, g_z);
    cudaGetSymbolAddress(&p_x, g_x);
    cudaGetSymbolAddress(&p_h, g_h);
    float* xbuf = (float*)p_x;
    float* hbuf = (float*)p_h;

    // One-time side stream + events (host resources; created on the first,
    // uncaptured, correctness call — only record/wait occur during capture).
    static cudaStream_t s2 = nullptr;
    static cudaEvent_t ev_fork = nullptr, ev_join = nullptr;
    if (!s2) {
        cudaStreamCreateWithFlags(&s2, cudaStreamNonBlocking);
        cudaEventCreateWithFlags(&ev_fork, cudaEventDisableTiming);
        cudaEventCreateWithFlags(&ev_join, cudaEventDisableTiming);
    }

    const int TPB = 256;
    cudaStream_t s0 = 0;

    // Fork: s2 runs the UNSCALED gemm (reads only harness inputs, writes xbuf);
    // s0 builds the CSR (g_z, g_esrc, g_dinv). Disjoint state — no race.
    cudaEventRecord(ev_fork, s0);
    cudaStreamWaitEvent(s2, ev_fork, 0);
    gemm64_kernel<<<N_NODES / 32, 256, 0, s2>>>(emb, W1, xbuf);
    cudaEventRecord(ev_join, s2);

    cudaMemsetAsync(p_z, 0, sizeof(ZeroRegion), s0);
    fill_kernel<<<(E + TPB - 1) / TPB, TPB, 0, s0>>>(src, dst, E);
    dinv_kernel<<<(N_NODES + TPB - 1) / TPB, TPB, 0, s0>>>();
    cudaStreamWaitEvent(s0, ev_join, 0);

    // ---- Layer 1: y' = relu(dinv*(Agg dinv[s]*x[s] + dinv*x) + b1)*dinv
    gather_kernel<1><<<N_NODES * 16 / TPB, TPB, 0, s0>>>(
        (const float4*)xbuf, (float4*)hbuf, (const float4*)b1, batch);

    // ---- Layer 2 aggregation + segmented pool flush
    gather_kernel<0><<<N_NODES * 16 / TPB, TPB, 0, s0>>>(
        (const float4*)hbuf, (float4*)xbuf, (const float4*)b2, batch);

    // ---- Head (W2/b2 + MLP)
    mlp_kernel<<<N_GRAPHS, H, 0, s0>>>(W2, b2, mW1, mb1, mW2, mb2, out);
}

// round 16
// speedup vs baseline: 1.3299x; 1.3299x over previous
#include <cuda_runtime.h>
#include <cuda_fp16.h>
#include <math.h>

#define N_NODES 100000
#define N_GRAPHS 1000
#define D 64
#define H 128
#define CAP 64            // max in-degree capacity (actual max ~32 for Poisson(10)+ring)
#define ZROW N_NODES      // zero-row index (stays zero: statics zero-init, never written)

// Scratch (alloc-free rule: __device__ globals). cursor/pool/cnt share one
// struct so a single memset clears all per-run state.
struct ZeroRegion {
    int   cursor[N_NODES];      // becomes in-degree after fill
    float pool[N_GRAPHS * D];
    float cnt[N_GRAPHS];
};
__device__ ZeroRegion g_z;
__device__ int     g_esrc[N_NODES * CAP];        // bucketed edge lists (25.6 MB)
__device__ __half2 g_x[(N_NODES + 1) * (D / 2)]; // fp16 features, 128B/row (+ zero row)
__device__ __half2 g_h[(N_NODES + 1) * (D / 2)]; // fp16 features, 128B/row (+ zero row)

// ---------------------------------------------------------------------------
// Bucketed CSR fill: cursor counts in-degree, esrc[d*CAP + pos] = s.
__global__ void fill_kernel(const int* __restrict__ src,
                            const int* __restrict__ dst, int E) {
    int i = blockIdx.x * blockDim.x + threadIdx.x;
    if (i >= E) return;
    int d = dst[i];
    int pos = atomicAdd(&g_z.cursor[d], 1);
    if (pos < CAP) g_esrc[(size_t)d * CAP + pos] = src[i];
}

// ---------------------------------------------------------------------------
// Y[N,32 half2] = half2( (X[N,64] @ W[64,64]) * rsqrt(deg[row]+1) )
// Each thread owns 2 adjacent columns (one half2): 256 thr = 8 rows x 32 h2.
__global__ void gemm64_kernel(const float* __restrict__ X,
                              const float* __restrict__ W,
                              __half2* __restrict__ Y) {
    __shared__ float sW[D * D];
    __shared__ float sx[32 * D];
    int t = threadIdx.x;
    int row0 = blockIdx.x * 32;
    for (int i = t; i < D * D; i += 256) sW[i] = W[i];
    for (int i = t; i < 32 * D; i += 256) sx[i] = X[row0 * D + i];
    __syncthreads();
    int j = (t & 31) * 2;     // column pair base
    int rg = t >> 5;          // row group 0..7, rows rg*4 .. rg*4+3
    float accA[4], accB[4];
#pragma unroll
    for (int i = 0; i < 4; i++) { accA[i] = 0.f; accB[i] = 0.f; }
#pragma unroll
    for (int k = 0; k < D; k++) {
        float wA = sW[k * D + j];
        float wB = sW[k * D + j + 1];
#pragma unroll
        for (int i = 0; i < 4; i++) {
            float xv = sx[(rg * 4 + i) * D + k];
            accA[i] += xv * wA;
            accB[i] += xv * wB;
        }
    }
#pragma unroll
    for (int i = 0; i < 4; i++) {
        int row = row0 + rg * 4 + i;
        float di = rsqrtf((float)(min(g_z.cursor[row], CAP) + 1));
        Y[row * (D / 2) + (j >> 1)] = __floats2half2_rn(accA[i] * di, accB[i] * di);
    }
}

// ---------------------------------------------------------------------------
// Gather, half-warp (16 lanes x 8B = one 128B line) per node. Input fp16
// (half2 pairs), pre-scaled by dinv[src]; accumulation in fp32.
//   t[n] = dinv[n] * (sum_{s in N(n)} x'[s] + x'[n])
//   MODE 1 (layer 1): out[n] = half(relu(t[n] + b) * dinv[n])  -> write g_h
//   MODE 0 (layer 2): block-level segmented pool flush (fp32 smem stage +
//                     fold along sorted-batch segments + sparse red.v4).
template <int MODE>
__global__ void __launch_bounds__(256, 6)
gather_kernel(const __half2* __restrict__ Xh,
              __half2* __restrict__ out,
              const float* __restrict__ bb,
              const int* __restrict__ batch) {
    int tid = threadIdx.x;
    int node = (blockIdx.x * blockDim.x + tid) >> 4;
    int lane = tid & 31;
    int hl = lane & 15;
    int deg = min(g_z.cursor[node], CAP);
    int maxdeg = max(deg, __shfl_xor_sync(0xffffffffu, deg, 16));
    const int* rowp = g_esrc + (size_t)node * CAP;
    float4 acc0 = make_float4(0.f, 0.f, 0.f, 0.f);
    float4 acc1 = make_float4(0.f, 0.f, 0.f, 0.f);
    for (int j = 0; j < maxdeg; j += 16) {
        int s = ((j + hl) < deg) ? rowp[j + hl] : ZROW;
#pragma unroll
        for (int i = 0; i < 16; i += 2) {
            int si0 = __shfl_sync(0xffffffffu, s, (lane & 16) + i);
            int si1 = __shfl_sync(0xffffffffu, s, (lane & 16) + i + 1);
            // 8B vector load: two half2 per lane (one 128B line per half-warp)
            const __half2* p0 = Xh + (size_t)si0 * (D / 2) + hl * 2;
            const __half2* p1 = Xh + (size_t)si1 * (D / 2) + hl * 2;
            __half2 v0a = p0[0], v0b = p0[1];
            __half2 v1a = p1[0], v1b = p1[1];
            float2 a0 = __half22float2(v0a);
            float2 b0 = __half22float2(v0b);
            float2 a1 = __half22float2(v1a);
            float2 b1 = __half22float2(v1b);
            acc0.x += a0.x; acc0.y += a0.y; acc0.z += b0.x; acc0.w += b0.y;
            acc1.x += a1.x; acc1.y += a1.y; acc1.z += b1.x; acc1.w += b1.y;
        }
    }
    // self term + merge accumulators
    float di = rsqrtf((float)(deg + 1));
    const __half2* ps = Xh + (size_t)node * (D / 2) + hl * 2;
    float2 sa = __half22float2(ps[0]);
    float2 sb = __half22float2(ps[1]);
    float4 o;
    o.x = (acc0.x + acc1.x + sa.x) * di;
    o.y = (acc0.y + acc1.y + sa.y) * di;
    o.z = (acc0.z + acc1.z + sb.x) * di;
    o.w = (acc0.w + acc1.w + sb.y) * di;
    if (MODE == 1) {
        const float4 b4v = *reinterpret_cast<const float4*>(bb + hl * 4);
        o.x = fmaxf(o.x + b4v.x, 0.f) * di;
        o.y = fmaxf(o.y + b4v.y, 0.f) * di;
        o.z = fmaxf(o.z + b4v.z, 0.f) * di;
        o.w = fmaxf(o.w + b4v.w, 0.f) * di;
        __half2* po = out + (size_t)node * (D / 2) + hl * 2;
        po[0] = __floats2half2_rn(o.x, o.y);
        po[1] = __floats2half2_rn(o.z, o.w);
    } else {
        // Stage z rows + graph ids in smem; fold segments; sparse flush.
        __shared__ float4 sZ[16][16];   // [node-in-block][column chunk]
        __shared__ int    sB[16];
        int nib = tid >> 4;             // node-in-block 0..15
        sZ[nib][hl] = o;
        if (hl == 0) sB[nib] = __ldg(batch + node);
        __syncthreads();
        if (tid < 16) {
            int c = tid;                // column chunk this thread folds
            float4 z = sZ[0][c];
            int curg = sB[0];
            int run = 1;
            for (int k = 1; k < 16; k++) {
                int bk = sB[k];
                float4 v = sZ[k][c];
                if (bk != curg) {
                    float* p = g_z.pool + curg * D + c * 4;
                    asm volatile("red.global.add.v4.f32 [%0], {%1, %2, %3, %4};"
                                 :: "l"(p), "f"(z.x), "f"(z.y), "f"(z.z), "f"(z.w)
                                 : "memory");
                    if (c == 0) atomicAdd(&g_z.cnt[curg], (float)run);
                    z = v; curg = bk; run = 1;
                } else {
                    z.x += v.x; z.y += v.y; z.z += v.z; z.w += v.w;
                    run++;
                }
            }
            float* p = g_z.pool + curg * D + c * 4;
            asm volatile("red.global.add.v4.f32 [%0], {%1, %2, %3, %4};"
                         :: "l"(p), "f"(z.x), "f"(z.y), "f"(z.z), "f"(z.w)
                         : "memory");
            if (c == 0) atomicAdd(&g_z.cnt[curg], (float)run);
        }
    }
}

// ---------------------------------------------------------------------------
// Head: q = mean(z) @ W2 + b2 ; out = sigmoid(relu(q @ mW1 + mb1) @ mW2 + mb2)
__global__ void mlp_kernel(const float* __restrict__ W2,
                           const float* __restrict__ b2,
                           const float* __restrict__ mW1,
                           const float* __restrict__ mb1,
                           const float* __restrict__ mW2,
                           const float* __restrict__ mb2,
                           float* __restrict__ out) {
    __shared__ float p[D];
    __shared__ float q[D];
    __shared__ float red[H];
    int g = blockIdx.x, t = threadIdx.x;
    if (t < D) {
        float c = fmaxf(g_z.cnt[g], 1.f);
        p[t] = g_z.pool[g * D + t] / c;
    }
    __syncthreads();
    if (t < D) {
        float a = b2[t];
#pragma unroll
        for (int k = 0; k < D; k++) a += p[k] * W2[k * D + t];
        q[t] = a;
    }
    __syncthreads();
    float acc = mb1[t];
#pragma unroll
    for (int k = 0; k < D; k++) acc += q[k] * mW1[k * H + t];
    red[t] = fmaxf(acc, 0.f) * mW2[t];
    __syncthreads();
    for (int s = H / 2; s > 0; s >>= 1) {
        if (t < s) red[t] += red[t + s];
        __syncthreads();
    }
    if (t == 0) out[g] = 1.f / (1.f + expf(-(red[0] + mb2[0])));
}

// ---------------------------------------------------------------------------
extern "C" void kernel_launch(void* const* d_in, const int* in_sizes, int n_in,
                              void* d_out, int out_size) {
    const int*   edge_index = (const int*)d_in[0];
    const int*   batch      = (const int*)d_in[1];
    const float* emb        = (const float*)d_in[2];
    const float* W1         = (const float*)d_in[3];
    const float* b1         = (const float*)d_in[4];
    const float* W2         = (const float*)d_in[5];
    const float* b2         = (const float*)d_in[6];
    const float* mW1        = (const float*)d_in[7];
    const float* mb1        = (const float*)d_in[8];
    const float* mW2        = (const float*)d_in[9];
    const float* mb2        = (const float*)d_in[10];
    float* out = (float*)d_out;

    int E = in_sizes[0] / 2;
    const int* src = edge_index;
    const int* dst = edge_index + E;

    void *p_z, *p_x, *p_h;
    cudaGetSymbolAddress(&p_z, g_z);
    cudaGetSymbolAddress(&p_x, g_x);
    cudaGetSymbolAddress(&p_h, g_h);
    __half2* xbuf = (__half2*)p_x;
    __half2* hbuf = (__half2*)p_h;

    const int TPB = 256;

    // One memset clears cursor + pool + cnt; then CSR fill.
    cudaMemsetAsync(p_z, 0, sizeof(ZeroRegion));
    fill_kernel<<<(E + TPB - 1) / TPB, TPB>>>(src, dst, E);

    // ---- Layer 1: x' = half((emb @ W1)*dinv) ; y' = half(relu(Agg + b1)*dinv)
    gemm64_kernel<<<N_NODES / 32, 256>>>(emb, W1, xbuf);
    gather_kernel<1><<<N_NODES * 16 / TPB, TPB>>>(xbuf, hbuf, b1, batch);

    // ---- Layer 2 aggregation + segmented pool flush
    gather_kernel<0><<<N_NODES * 16 / TPB, TPB>>>(hbuf, xbuf, b2, batch);

    // ---- Head (W2/b2 + MLP)
    mlp_kernel<<<N_GRAPHS, H>>>(W2, b2, mW1, mb1, mW2, mb2, out);
}